// round 4
// baseline (speedup 1.0000x reference)
#include <cuda_runtime.h>
#include <cuda_fp16.h>

// SSIM loss: B=64, C=1, H=W=512, 11x11 uniform box window (1/121), SAME zero padding.
// out = 1 - mean( ret * cs ).
//
// Separable box filter, 4 sums per pixel: E1=box(x), E2=box(y), E3=box(xy), E4=box(x^2+y^2).
// Thread-private 4-column group of a 32-row strip:
//   - horizontal 11-tap sums as depth-4 trees + parallel slide deltas
//   - carried loop state = fp16x4-PACKED h-sums (8 regs) -> low register pressure
//   - vertical running sums via per-thread fp16 ring in shared (45KB -> 5 blocks/SM)
//   - exact telescoping: vertical sums add/subtract the fp16-ROUNDED values
//   - per-row loads issued before consuming previous row's h-sums (latency overlap)
// 1024 blocks for load balance; single kernel, last-block reduction.

#define WID    512
#define HEI    512
#define RH     32
#define TPB    128
#define NSTRIP 16
#define NBLK   1024
#define RING_BYTES (11 * 4 * TPB * (int)sizeof(uint2))  // 45056 B

__device__ float    g_part[NBLK];
__device__ unsigned g_cnt;   // zero-init; last block resets to 0 each replay

__device__ __forceinline__ uint2 pack4(float4 v) {
    __half2 lo = __floats2half2_rn(v.x, v.y);
    __half2 hi = __floats2half2_rn(v.z, v.w);
    uint2 u;
    u.x = *reinterpret_cast<unsigned*>(&lo);
    u.y = *reinterpret_cast<unsigned*>(&hi);
    return u;
}

__device__ __forceinline__ float4 unpack4(uint2 u) {
    __half2 lo = *reinterpret_cast<__half2*>(&u.x);
    __half2 hi = *reinterpret_cast<__half2*>(&u.y);
    float2 a = __half22float2(lo);
    float2 b = __half22float2(hi);
    return make_float4(a.x, a.y, b.x, b.y);
}

// numerator/denominator of the per-pixel SSIM value (division deferred)
__device__ __forceinline__ void ssim_nd(float e1, float e2, float e3, float e4,
                                        float w, float w2, float& N, float& D) {
    const float C1 = 1.6384f;
    const float C2 = 14.7456f;
    float P  = e1 * e2;
    float Q  = fmaf(e1, e1, e2 * e2);
    float A  = w2 * P;
    float B  = w2 * Q;
    float n1 = fmaf(2.f, A, C1);
    float d1 = B + C1;
    float n2 = fmaf(2.f * w, e3, fmaf(-2.f, A, C2));
    float d2 = fmaf(w, e4, C2 - B);
    N = n1 * n2;
    D = d1 * d2;
}

__global__ void __launch_bounds__(TPB, 5)
ssim_k(const float* __restrict__ img1, const float* __restrict__ img2,
       const float* __restrict__ window, float* __restrict__ out)
{
    extern __shared__ uint2 ring[];   // [(slot*4+q)*TPB + h], fp16x4 per entry
    const int h     = threadIdx.x;
    const int b     = blockIdx.x >> 4;
    const int strip = blockIdx.x & (NSTRIP - 1);
    const int r0    = strip * RH;
    const int c0    = h << 2;

    const float w  = __ldg(window);    // 1/121
    const float w2 = w * w;

    const float* p1 = img1 + (size_t)b * (HEI * WID) + (c0 - 8);
    const float* p2 = img2 + (size_t)b * (HEI * WID) + (c0 - 8);

    const bool kp0 = (h >= 2);
    const bool kp1 = (h >= 1);
    const bool kp3 = (h <= 126);
    const bool kp4 = (h <= 125);

    const float4 z4 = make_float4(0.f, 0.f, 0.f, 0.f);
    const uint2  zu = make_uint2(0u, 0u);
    #pragma unroll
    for (int s = 0; s < 44; s++) ring[s * TPB + h] = zu;

    float4 vs0 = z4, vs1 = z4, vs2 = z4, vs3 = z4;
    float acc = 0.f;
    int slot = 0;

    float xr[20], yr[20];   // transient raw row
    uint2 pn[4];            // carried state: packed h-sums of current row

    auto load_row = [&](int r) {
        bool v = ((unsigned)r < (unsigned)HEI);
        const float4* q1 = (const float4*)(p1 + r * WID);
        const float4* q2 = (const float4*)(p2 + r * WID);
        float4 t;
        t = (v && kp0) ? __ldg(q1 + 0) : z4; xr[0]=t.x; xr[1]=t.y; xr[2]=t.z; xr[3]=t.w;
        t = (v && kp1) ? __ldg(q1 + 1) : z4; xr[4]=t.x; xr[5]=t.y; xr[6]=t.z; xr[7]=t.w;
        t =  v         ? __ldg(q1 + 2) : z4; xr[8]=t.x; xr[9]=t.y; xr[10]=t.z; xr[11]=t.w;
        t = (v && kp3) ? __ldg(q1 + 3) : z4; xr[12]=t.x; xr[13]=t.y; xr[14]=t.z; xr[15]=t.w;
        t = (v && kp4) ? __ldg(q1 + 4) : z4; xr[16]=t.x; xr[17]=t.y; xr[18]=t.z; xr[19]=t.w;
        t = (v && kp0) ? __ldg(q2 + 0) : z4; yr[0]=t.x; yr[1]=t.y; yr[2]=t.z; yr[3]=t.w;
        t = (v && kp1) ? __ldg(q2 + 1) : z4; yr[4]=t.x; yr[5]=t.y; yr[6]=t.z; yr[7]=t.w;
        t =  v         ? __ldg(q2 + 2) : z4; yr[8]=t.x; yr[9]=t.y; yr[10]=t.z; yr[11]=t.w;
        t = (v && kp3) ? __ldg(q2 + 3) : z4; yr[12]=t.x; yr[13]=t.y; yr[14]=t.z; yr[15]=t.w;
        t = (v && kp4) ? __ldg(q2 + 4) : z4; yr[16]=t.x; yr[17]=t.y; yr[18]=t.z; yr[19]=t.w;
    };

    // horizontal 11-tap sums of the transient raw row -> packed fp16x4 state
    auto comp_h = [&]() {
        float4 h1;
        {
            float d1a = xr[14]-xr[3], d1b = xr[15]-xr[4], d1c = xr[16]-xr[5];
            float s01 = xr[3]+xr[4], s23 = xr[5]+xr[6], s45 = xr[7]+xr[8];
            float s67 = xr[9]+xr[10], s89 = xr[11]+xr[12];
            h1.x = ((s01+s23)+(s45+s67)) + (s89+xr[13]);
            h1.y = h1.x + d1a; h1.z = h1.y + d1b; h1.w = h1.z + d1c;
        }
        float4 h2;
        {
            float d1a = yr[14]-yr[3], d1b = yr[15]-yr[4], d1c = yr[16]-yr[5];
            float s01 = yr[3]+yr[4], s23 = yr[5]+yr[6], s45 = yr[7]+yr[8];
            float s67 = yr[9]+yr[10], s89 = yr[11]+yr[12];
            h2.x = ((s01+s23)+(s45+s67)) + (s89+yr[13]);
            h2.y = h2.x + d1a; h2.z = h2.y + d1b; h2.w = h2.z + d1c;
        }
        float4 h3;
        {
            float p3 = xr[3]*yr[3], p4 = xr[4]*yr[4], p5 = xr[5]*yr[5];
            float cB = fmaf(xr[9],yr[9], fmaf(xr[8],yr[8], fmaf(xr[7],yr[7], xr[6]*yr[6])));
            float cC = fmaf(xr[13],yr[13], fmaf(xr[12],yr[12], fmaf(xr[11],yr[11], xr[10]*yr[10])));
            h3.x = ((p3+p4)+p5) + (cB+cC);
            float u1 = fmaf(xr[14],yr[14], -p3);
            float u2 = fmaf(xr[15],yr[15], -p4);
            float u3 = fmaf(xr[16],yr[16], -p5);
            h3.y = h3.x + u1; h3.z = h3.y + u2; h3.w = h3.z + u3;
        }
        float4 h4;
        {
            float q3 = fmaf(yr[3],yr[3], xr[3]*xr[3]);
            float q4 = fmaf(yr[4],yr[4], xr[4]*xr[4]);
            float q5 = fmaf(yr[5],yr[5], xr[5]*xr[5]);
            float cB = xr[6]*xr[6];
            cB = fmaf(yr[6],yr[6],cB); cB = fmaf(xr[7],xr[7],cB); cB = fmaf(yr[7],yr[7],cB);
            cB = fmaf(xr[8],xr[8],cB); cB = fmaf(yr[8],yr[8],cB);
            cB = fmaf(xr[9],xr[9],cB); cB = fmaf(yr[9],yr[9],cB);
            float cC = xr[10]*xr[10];
            cC = fmaf(yr[10],yr[10],cC); cC = fmaf(xr[11],xr[11],cC); cC = fmaf(yr[11],yr[11],cC);
            cC = fmaf(xr[12],xr[12],cC); cC = fmaf(yr[12],yr[12],cC);
            cC = fmaf(xr[13],xr[13],cC); cC = fmaf(yr[13],yr[13],cC);
            h4.x = ((q3+q4)+q5) + (cB+cC);
            float v1 = fmaf(xr[14],xr[14], -q3); v1 = fmaf(yr[14],yr[14], v1);
            float v2 = fmaf(xr[15],xr[15], -q4); v2 = fmaf(yr[15],yr[15], v2);
            float v3 = fmaf(xr[16],xr[16], -q5); v3 = fmaf(yr[16],yr[16], v3);
            h4.y = h4.x + v1; h4.z = h4.y + v2; h4.w = h4.z + v3;
        }
        pn[0] = pack4(h1); pn[1] = pack4(h2); pn[2] = pack4(h3); pn[3] = pack4(h4);
    };

    // ring + vertical update (+ optional emit) from the packed state
    auto process = [&](bool emit) {
        uint2* rp = ring + slot * (4 * TPB) + h;
        uint2 po0 = rp[0];
        uint2 po1 = rp[TPB];
        uint2 po2 = rp[2*TPB];
        uint2 po3 = rp[3*TPB];
        rp[0] = pn[0]; rp[TPB] = pn[1]; rp[2*TPB] = pn[2]; rp[3*TPB] = pn[3];
        float4 n0 = unpack4(pn[0]), o0 = unpack4(po0);
        float4 n1 = unpack4(pn[1]), o1 = unpack4(po1);
        float4 n2 = unpack4(pn[2]), o2 = unpack4(po2);
        float4 n3 = unpack4(pn[3]), o3 = unpack4(po3);
        vs0.x += n0.x-o0.x; vs0.y += n0.y-o0.y; vs0.z += n0.z-o0.z; vs0.w += n0.w-o0.w;
        vs1.x += n1.x-o1.x; vs1.y += n1.y-o1.y; vs1.z += n1.z-o1.z; vs1.w += n1.w-o1.w;
        vs2.x += n2.x-o2.x; vs2.y += n2.y-o2.y; vs2.z += n2.z-o2.z; vs2.w += n2.w-o2.w;
        vs3.x += n3.x-o3.x; vs3.y += n3.y-o3.y; vs3.z += n3.z-o3.z; vs3.w += n3.w-o3.w;
        slot = (slot == 10) ? 0 : slot + 1;

        if (emit) {
            float N0, D0, N1, D1, N2, D2, N3, D3;
            ssim_nd(vs0.x, vs1.x, vs2.x, vs3.x, w, w2, N0, D0);
            ssim_nd(vs0.y, vs1.y, vs2.y, vs3.y, w, w2, N1, D1);
            ssim_nd(vs0.z, vs1.z, vs2.z, vs3.z, w, w2, N2, D2);
            ssim_nd(vs0.w, vs1.w, vs2.w, vs3.w, w, w2, N3, D3);
            // a/b + c/d = (a*d + c*b) / (b*d) : 2 divides instead of 4
            acc += __fdividef(fmaf(N0, D1, N1 * D0), D0 * D1);
            acc += __fdividef(fmaf(N2, D3, N3 * D2), D2 * D3);
        }
    };

    // ---- row loop: load(r+1) || process(r) ----
    int r = r0 - 5;
    load_row(r);
    comp_h();
    #pragma unroll 2
    for (int i = 0; i < 10; ++i) {            // warmup rows, no emit
        load_row(r + 1);
        process(false);
        comp_h();
        ++r;
    }
    #pragma unroll 2
    for (int i = 0; i < RH - 1; ++i) {        // main rows, emit
        load_row(r + 1);
        process(true);
        comp_h();
        ++r;
    }
    process(true);                            // last row

    // ---- block reduction ----
    #pragma unroll
    for (int o = 16; o > 0; o >>= 1)
        acc += __shfl_xor_sync(0xffffffffu, acc, o);
    __shared__ float wsum[4];
    __shared__ int lastflag;
    int wid = h >> 5, lane = h & 31;
    if (lane == 0) wsum[wid] = acc;
    __syncthreads();
    if (h == 0) {
        float bs = (wsum[0] + wsum[1]) + (wsum[2] + wsum[3]);
        g_part[blockIdx.x] = bs;
        __threadfence();
        unsigned t = atomicAdd(&g_cnt, 1u);
        lastflag = (t == NBLK - 1) ? 1 : 0;
    }
    __syncthreads();

    if (lastflag) {
        volatile float* vp = g_part;
        double d = 0.0;
        #pragma unroll
        for (int k = 0; k < NBLK / TPB; ++k)
            d += (double)vp[h + k * TPB];
        #pragma unroll
        for (int o = 16; o > 0; o >>= 1)
            d += __shfl_xor_sync(0xffffffffu, d, o);
        __shared__ double dsum[4];
        if (lane == 0) dsum[wid] = d;
        __syncthreads();
        if (h == 0) {
            double tot = (dsum[0] + dsum[1]) + (dsum[2] + dsum[3]);
            out[0] = (float)(1.0 - tot * (1.0 / 16777216.0));
            g_cnt = 0;
        }
    }
}

extern "C" void kernel_launch(void* const* d_in, const int* in_sizes, int n_in,
                              void* d_out, int out_size)
{
    const float* img1   = (const float*)d_in[0];
    const float* img2   = (const float*)d_in[1];
    const float* window = (const float*)d_in[2];
    (void)in_sizes; (void)n_in; (void)out_size;

    cudaFuncSetAttribute(ssim_k,
                         cudaFuncAttributeMaxDynamicSharedMemorySize, RING_BYTES);
    ssim_k<<<NBLK, TPB, RING_BYTES>>>(img1, img2, window, (float*)d_out);
}

// round 5
// speedup vs baseline: 2.1754x; 2.1754x over previous
#include <cuda_runtime.h>
#include <cuda_fp16.h>

// SSIM loss: B=64, C=1, H=W=512, 11x11 uniform box (1/121), SAME zero padding.
// out = 1 - mean( ret * cs ).
//
// E1=box(x), E2=box(y), E3=box(xy), E4=box(x^2+y^2); separable box filter.
// Block = one 64-row strip of one image; thread owns 4 columns.
//   - cooperative SMEM row staging: block loads each 528-float row span ONCE
//     (1-2 LDG.128/thread/image), threads read spans via conflict-free LDS.128
//   - ping-pong staging buffers; LDG for row r+1 issued before processing row r
//   - horizontal 11-tap sums as trees + parallel slide deltas
//   - vertical running sums via per-thread fp16x4 ring in shared (exact telescoping)
// smem = 45KB ring + 8.25KB staging = 53.5KB -> 4 blocks/SM, 512 blocks = 1 wave.

#define WID    512
#define HEI    512
#define RH     64
#define TPB    128
#define NBLK   512
#define RING_U2    (11 * 4 * TPB)          // 5632 uint2 = 45056 B
#define STAGE_F4   132                     // 528 floats per row span
#define STAGE_OFF  (RING_U2 * 8)           // byte offset of staging area
#define SMEM_BYTES (STAGE_OFF + 4 * STAGE_F4 * 16)   // 45056 + 8448 = 53504

__device__ float    g_part[NBLK];
__device__ unsigned g_cnt;   // zero-init; last block resets each replay

__device__ __forceinline__ uint2 pack4(float4 v) {
    __half2 lo = __floats2half2_rn(v.x, v.y);
    __half2 hi = __floats2half2_rn(v.z, v.w);
    uint2 u;
    u.x = *reinterpret_cast<unsigned*>(&lo);
    u.y = *reinterpret_cast<unsigned*>(&hi);
    return u;
}

__device__ __forceinline__ float4 unpack4(uint2 u) {
    __half2 lo = *reinterpret_cast<__half2*>(&u.x);
    __half2 hi = *reinterpret_cast<__half2*>(&u.y);
    float2 a = __half22float2(lo);
    float2 b = __half22float2(hi);
    return make_float4(a.x, a.y, b.x, b.y);
}

__device__ __forceinline__ void ssim_nd(float e1, float e2, float e3, float e4,
                                        float w, float w2, float& N, float& D) {
    const float C1 = 1.6384f;
    const float C2 = 14.7456f;
    float P  = e1 * e2;
    float Q  = fmaf(e1, e1, e2 * e2);
    float A  = w2 * P;
    float B  = w2 * Q;
    float n1 = fmaf(2.f, A, C1);
    float d1 = B + C1;
    float n2 = fmaf(2.f * w, e3, fmaf(-2.f, A, C2));
    float d2 = fmaf(w, e4, C2 - B);
    N = n1 * n2;
    D = d1 * d2;
}

__global__ void __launch_bounds__(TPB, 4)
ssim_k(const float* __restrict__ img1, const float* __restrict__ img2,
       const float* __restrict__ window, float* __restrict__ out)
{
    extern __shared__ unsigned char smem_raw[];
    uint2*  ring = (uint2*)smem_raw;                    // fp16x4 ring
    float4* stg  = (float4*)(smem_raw + STAGE_OFF);     // [buf][img][132]

    const int h     = threadIdx.x;
    const int b     = blockIdx.x >> 3;
    const int strip = blockIdx.x & 7;
    const int r0    = strip * RH;

    const float w  = __ldg(window);    // 1/121
    const float w2 = w * w;

    const float* base1 = img1 + (size_t)b * (HEI * WID);
    const float* base2 = img2 + (size_t)b * (HEI * WID);

    const float4 z4 = make_float4(0.f, 0.f, 0.f, 0.f);
    const uint2  zu = make_uint2(0u, 0u);
    #pragma unroll
    for (int s = 0; s < 44; s++) ring[s * TPB + h] = zu;

    float4 vs0 = z4, vs1 = z4, vs2 = z4, vs3 = z4;
    float acc = 0.f;
    int slot = 0;

    // staging index i holds image columns [4i-8, 4i-4); thread h consumes i=h..h+4
    const bool ok0 = (h >= 2);          // i0 = h      valid iff 2 <= h < 130 (h<128 always)
    const bool xtr = (h < 4);           // i1 = 128+h  (only threads 0..3)
    const bool ok1 = (h < 2);           // i1 valid iff 128+h < 130

    float4 a0, a1, b0, b1;              // in-flight row (carried across process)

    auto ldg_row = [&](int r) {
        bool v = ((unsigned)r < (unsigned)HEI);
        const float4* q1 = (const float4*)(base1 + r * WID);
        const float4* q2 = (const float4*)(base2 + r * WID);
        a0 = (v && ok0) ? __ldg(q1 + (h - 2)) : z4;
        b0 = (v && ok0) ? __ldg(q2 + (h - 2)) : z4;
        if (xtr) {
            a1 = (v && ok1) ? __ldg(q1 + (126 + h)) : z4;
            b1 = (v && ok1) ? __ldg(q2 + (126 + h)) : z4;
        }
    };

    auto sts_row = [&](int buf) {
        float4* s0 = stg + (buf * 2 + 0) * STAGE_F4;
        float4* s1 = stg + (buf * 2 + 1) * STAGE_F4;
        s0[h] = a0;
        s1[h] = b0;
        if (xtr) { s0[128 + h] = a1; s1[128 + h] = b1; }
    };

    auto process = [&](int buf, bool emit) {
        const float4* s0 = stg + (buf * 2 + 0) * STAGE_F4;
        const float4* s1 = stg + (buf * 2 + 1) * STAGE_F4;
        float xr[20], yr[20];
        #pragma unroll
        for (int k = 0; k < 5; k++) {
            float4 t = s0[h + k];
            xr[4*k+0]=t.x; xr[4*k+1]=t.y; xr[4*k+2]=t.z; xr[4*k+3]=t.w;
            t = s1[h + k];
            yr[4*k+0]=t.x; yr[4*k+1]=t.y; yr[4*k+2]=t.z; yr[4*k+3]=t.w;
        }

        // ---- horizontal 11-tap sums (trees + parallel slide deltas) ----
        float4 h1;
        {
            float d1a = xr[14]-xr[3], d1b = xr[15]-xr[4], d1c = xr[16]-xr[5];
            float s01 = xr[3]+xr[4], s23 = xr[5]+xr[6], s45 = xr[7]+xr[8];
            float s67 = xr[9]+xr[10], s89 = xr[11]+xr[12];
            h1.x = ((s01+s23)+(s45+s67)) + (s89+xr[13]);
            h1.y = h1.x + d1a; h1.z = h1.y + d1b; h1.w = h1.z + d1c;
        }
        float4 h2;
        {
            float d1a = yr[14]-yr[3], d1b = yr[15]-yr[4], d1c = yr[16]-yr[5];
            float s01 = yr[3]+yr[4], s23 = yr[5]+yr[6], s45 = yr[7]+yr[8];
            float s67 = yr[9]+yr[10], s89 = yr[11]+yr[12];
            h2.x = ((s01+s23)+(s45+s67)) + (s89+yr[13]);
            h2.y = h2.x + d1a; h2.z = h2.y + d1b; h2.w = h2.z + d1c;
        }
        float4 h3;
        {
            float p3 = xr[3]*yr[3], p4 = xr[4]*yr[4], p5 = xr[5]*yr[5];
            float cB = fmaf(xr[9],yr[9], fmaf(xr[8],yr[8], fmaf(xr[7],yr[7], xr[6]*yr[6])));
            float cC = fmaf(xr[13],yr[13], fmaf(xr[12],yr[12], fmaf(xr[11],yr[11], xr[10]*yr[10])));
            h3.x = ((p3+p4)+p5) + (cB+cC);
            float u1 = fmaf(xr[14],yr[14], -p3);
            float u2 = fmaf(xr[15],yr[15], -p4);
            float u3 = fmaf(xr[16],yr[16], -p5);
            h3.y = h3.x + u1; h3.z = h3.y + u2; h3.w = h3.z + u3;
        }
        float4 h4;
        {
            float q3 = fmaf(yr[3],yr[3], xr[3]*xr[3]);
            float q4 = fmaf(yr[4],yr[4], xr[4]*xr[4]);
            float q5 = fmaf(yr[5],yr[5], xr[5]*xr[5]);
            float cB = xr[6]*xr[6];
            cB = fmaf(yr[6],yr[6],cB); cB = fmaf(xr[7],xr[7],cB); cB = fmaf(yr[7],yr[7],cB);
            cB = fmaf(xr[8],xr[8],cB); cB = fmaf(yr[8],yr[8],cB);
            cB = fmaf(xr[9],xr[9],cB); cB = fmaf(yr[9],yr[9],cB);
            float cC = xr[10]*xr[10];
            cC = fmaf(yr[10],yr[10],cC); cC = fmaf(xr[11],xr[11],cC); cC = fmaf(yr[11],yr[11],cC);
            cC = fmaf(xr[12],xr[12],cC); cC = fmaf(yr[12],yr[12],cC);
            cC = fmaf(xr[13],xr[13],cC); cC = fmaf(yr[13],yr[13],cC);
            h4.x = ((q3+q4)+q5) + (cB+cC);
            float v1 = fmaf(xr[14],xr[14], -q3); v1 = fmaf(yr[14],yr[14], v1);
            float v2 = fmaf(xr[15],xr[15], -q4); v2 = fmaf(yr[15],yr[15], v2);
            float v3 = fmaf(xr[16],xr[16], -q5); v3 = fmaf(yr[16],yr[16], v3);
            h4.y = h4.x + v1; h4.z = h4.y + v2; h4.w = h4.z + v3;
        }

        // ---- fp16 ring + vertical running sums (exact telescoping) ----
        uint2* rp = ring + slot * (4 * TPB) + h;
        uint2 po0 = rp[0];
        uint2 po1 = rp[TPB];
        uint2 po2 = rp[2*TPB];
        uint2 po3 = rp[3*TPB];
        uint2 pn0 = pack4(h1), pn1 = pack4(h2), pn2 = pack4(h3), pn3 = pack4(h4);
        rp[0] = pn0; rp[TPB] = pn1; rp[2*TPB] = pn2; rp[3*TPB] = pn3;
        float4 n0 = unpack4(pn0), o0 = unpack4(po0);
        float4 n1 = unpack4(pn1), o1 = unpack4(po1);
        float4 n2 = unpack4(pn2), o2 = unpack4(po2);
        float4 n3 = unpack4(pn3), o3 = unpack4(po3);
        vs0.x += n0.x-o0.x; vs0.y += n0.y-o0.y; vs0.z += n0.z-o0.z; vs0.w += n0.w-o0.w;
        vs1.x += n1.x-o1.x; vs1.y += n1.y-o1.y; vs1.z += n1.z-o1.z; vs1.w += n1.w-o1.w;
        vs2.x += n2.x-o2.x; vs2.y += n2.y-o2.y; vs2.z += n2.z-o2.z; vs2.w += n2.w-o2.w;
        vs3.x += n3.x-o3.x; vs3.y += n3.y-o3.y; vs3.z += n3.z-o3.z; vs3.w += n3.w-o3.w;
        slot = (slot == 10) ? 0 : slot + 1;

        if (emit) {
            float N0, D0, N1, D1, N2, D2, N3, D3;
            ssim_nd(vs0.x, vs1.x, vs2.x, vs3.x, w, w2, N0, D0);
            ssim_nd(vs0.y, vs1.y, vs2.y, vs3.y, w, w2, N1, D1);
            ssim_nd(vs0.z, vs1.z, vs2.z, vs3.z, w, w2, N2, D2);
            ssim_nd(vs0.w, vs1.w, vs2.w, vs3.w, w, w2, N3, D3);
            acc += __fdividef(fmaf(N0, D1, N1 * D0), D0 * D1);
            acc += __fdividef(fmaf(N2, D3, N3 * D2), D2 * D3);
        }
    };

    // ---- row pipeline: rows r0-5 .. r0+58 (74 rows), emit last 64 ----
    int r = r0 - 5;
    ldg_row(r);
    sts_row(0);
    __syncthreads();
    int pp = 0;

    #pragma unroll 2
    for (int i = 0; i < 10; ++i) {            // warmup, no emit
        ldg_row(r + 1);
        process(pp, false);
        sts_row(pp ^ 1);
        __syncthreads();
        pp ^= 1; ++r;
    }
    #pragma unroll 2
    for (int i = 0; i < 63; ++i) {            // main, emit
        ldg_row(r + 1);
        process(pp, true);
        sts_row(pp ^ 1);
        __syncthreads();
        pp ^= 1; ++r;
    }
    process(pp, true);                        // final row

    // ---- block reduction + last-block finish ----
    #pragma unroll
    for (int o = 16; o > 0; o >>= 1)
        acc += __shfl_xor_sync(0xffffffffu, acc, o);
    __shared__ float wsum[4];
    __shared__ int lastflag;
    int wid = h >> 5, lane = h & 31;
    if (lane == 0) wsum[wid] = acc;
    __syncthreads();
    if (h == 0) {
        float bs = (wsum[0] + wsum[1]) + (wsum[2] + wsum[3]);
        g_part[blockIdx.x] = bs;
        __threadfence();
        unsigned t = atomicAdd(&g_cnt, 1u);
        lastflag = (t == NBLK - 1) ? 1 : 0;
    }
    __syncthreads();

    if (lastflag) {
        volatile float* vp = g_part;
        double d = 0.0;
        #pragma unroll
        for (int k = 0; k < NBLK / TPB; ++k)
            d += (double)vp[h + k * TPB];
        #pragma unroll
        for (int o = 16; o > 0; o >>= 1)
            d += __shfl_xor_sync(0xffffffffu, d, o);
        __shared__ double dsum[4];
        if (lane == 0) dsum[wid] = d;
        __syncthreads();
        if (h == 0) {
            double tot = (dsum[0] + dsum[1]) + (dsum[2] + dsum[3]);
            out[0] = (float)(1.0 - tot * (1.0 / 16777216.0));
            g_cnt = 0;
        }
    }
}

extern "C" void kernel_launch(void* const* d_in, const int* in_sizes, int n_in,
                              void* d_out, int out_size)
{
    const float* img1   = (const float*)d_in[0];
    const float* img2   = (const float*)d_in[1];
    const float* window = (const float*)d_in[2];
    (void)in_sizes; (void)n_in; (void)out_size;

    cudaFuncSetAttribute(ssim_k,
                         cudaFuncAttributeMaxDynamicSharedMemorySize, SMEM_BYTES);
    ssim_k<<<NBLK, TPB, SMEM_BYTES>>>(img1, img2, window, (float*)d_out);
}

// round 6
// speedup vs baseline: 2.2044x; 1.0133x over previous
#include <cuda_runtime.h>

// SSIM loss: B=64, C=1, H=W=512, 11x11 uniform box (1/121), SAME zero padding.
// out = 1 - mean( ret * cs ).
//
// E1=box(x), E2=box(y), E3=box(xy), E4=box(x^2+y^2); separable box filter.
// Block = one 64-row strip; thread owns 4 output columns.
//   - staging holds (x,y)-INTERLEAVED pairs in two planes -> 8 conflict-free
//     LDS.128 per row deliver f32x2 pairs directly
//   - horizontal sums computed with packed f32x2 PTX (FFMA2/FADD2):
//     E1&E2 in one packed stream, E4 as packed (Sum x^2, Sum y^2)
//   - vertical running sums packed per column: (E1,E2) and (E3,E4) f32x2
//   - ring stores bf16x2 per column-quantity-pair (exact telescoping: the
//     rounded value added is the value later subtracted); unpack = ALU shifts
// smem = 45KB ring + 8.25KB staging = 53.5KB -> 4 blocks/SM, 512 blocks = 1 wave.

#define WID    512
#define HEI    512
#define RH     64
#define TPB    128
#define NBLK   512
#define RING_BYTES  (11 * 2 * TPB * 16)               // 11 slots * 2 uint4 * 128 thr = 45056
#define STAGE_OFF   RING_BYTES
#define STAGE_F4    132
#define SMEM_BYTES  (STAGE_OFF + 4 * STAGE_F4 * 16)   // + 8448 = 53504

typedef unsigned long long u64;

__device__ float    g_part[NBLK];
__device__ unsigned g_cnt;

// ---- f32x2 packed helpers ----
__device__ __forceinline__ u64 pk2(float lo, float hi) {
    u64 r; asm("mov.b64 %0,{%1,%2};" : "=l"(r) : "f"(lo), "f"(hi)); return r;
}
__device__ __forceinline__ float2 upk(u64 a) {
    float2 v; asm("mov.b64 {%0,%1},%2;" : "=f"(v.x), "=f"(v.y) : "l"(a)); return v;
}
__device__ __forceinline__ u64 add2(u64 a, u64 b) {
    u64 r; asm("add.rn.f32x2 %0,%1,%2;" : "=l"(r) : "l"(a), "l"(b)); return r;
}
__device__ __forceinline__ u64 mul2(u64 a, u64 b) {
    u64 r; asm("mul.rn.f32x2 %0,%1,%2;" : "=l"(r) : "l"(a), "l"(b)); return r;
}
__device__ __forceinline__ u64 fma2(u64 a, u64 b, u64 c) {
    u64 r; asm("fma.rn.f32x2 %0,%1,%2,%3;" : "=l"(r) : "l"(a), "l"(b), "l"(c)); return r;
}
// a - b  ==  fma(b, -1, a)
#define NEG1_PAIR 0xBF800000BF800000ull
__device__ __forceinline__ u64 sub2(u64 a, u64 b) { return fma2(b, NEG1_PAIR, a); }

// ---- bf16x2 ring pack/unpack ----
__device__ __forceinline__ unsigned pkbf(float lo, float hi) {
    unsigned r; asm("cvt.rn.bf16x2.f32 %0,%1,%2;" : "=r"(r) : "f"(hi), "f"(lo)); return r;
}
__device__ __forceinline__ u64 upbf(unsigned v) {   // bf16x2 -> f32x2 (lo,hi)
    unsigned lo = v << 16, hi = v & 0xffff0000u;
    u64 r; asm("mov.b64 %0,{%1,%2};" : "=l"(r) : "r"(lo), "r"(hi)); return r;
}

__device__ __forceinline__ void ssim_nd(float e1, float e2, float e3, float e4,
                                        float w, float w2, float& N, float& D) {
    const float C1 = 1.6384f;
    const float C2 = 14.7456f;
    float P  = e1 * e2;
    float Q  = fmaf(e1, e1, e2 * e2);
    float A  = w2 * P;
    float B  = w2 * Q;
    float n1 = fmaf(2.f, A, C1);
    float d1 = B + C1;
    float n2 = fmaf(2.f * w, e3, fmaf(-2.f, A, C2));
    float d2 = fmaf(w, e4, C2 - B);
    N = n1 * n2;
    D = d1 * d2;
}

__global__ void __launch_bounds__(TPB, 4)
ssim_k(const float* __restrict__ img1, const float* __restrict__ img2,
       const float* __restrict__ window, float* __restrict__ out)
{
    extern __shared__ unsigned char smem_raw[];
    uint4*  ring = (uint4*)smem_raw;                   // [slot][2][TPB]
    float4* stg  = (float4*)(smem_raw + STAGE_OFF);    // [buf][plane][132]

    const int h     = threadIdx.x;
    const int b     = blockIdx.x >> 3;
    const int strip = blockIdx.x & 7;
    const int r0    = strip * RH;

    const float w  = __ldg(window);    // 1/121
    const float w2 = w * w;

    const float* base1 = img1 + (size_t)b * (HEI * WID);
    const float* base2 = img2 + (size_t)b * (HEI * WID);

    const float4 z4 = make_float4(0.f, 0.f, 0.f, 0.f);
    const uint4  zu = make_uint4(0u, 0u, 0u, 0u);
    #pragma unroll
    for (int s = 0; s < 22; s++) ring[s * TPB + h] = zu;

    u64 V12[4] = {0,0,0,0};    // per-col packed (VE1, VE2)
    u64 V34[4] = {0,0,0,0};    // per-col packed (VE3, VE4)
    float acc = 0.f;
    int slot = 0;

    const bool ok0 = (h >= 2);
    const bool xtr = (h < 4);
    const bool ok1 = (h < 2);

    float4 a0, a1, b0, b1;     // in-flight GMEM row

    auto ldg_row = [&](int r) {
        bool v = ((unsigned)r < (unsigned)HEI);
        const float4* q1 = (const float4*)(base1 + r * WID);
        const float4* q2 = (const float4*)(base2 + r * WID);
        a0 = (v && ok0) ? __ldg(q1 + (h - 2)) : z4;
        b0 = (v && ok0) ? __ldg(q2 + (h - 2)) : z4;
        if (xtr) {
            a1 = (v && ok1) ? __ldg(q1 + (126 + h)) : z4;
            b1 = (v && ok1) ? __ldg(q2 + (126 + h)) : z4;
        }
    };

    // interleave (x,y): T0[i] = cols {4i-8,4i-7}, T1[i] = cols {4i-6,4i-5}
    auto sts_row = [&](int buf) {
        float4* t0 = stg + (buf * 2 + 0) * STAGE_F4;
        float4* t1 = stg + (buf * 2 + 1) * STAGE_F4;
        t0[h] = make_float4(a0.x, b0.x, a0.y, b0.y);
        t1[h] = make_float4(a0.z, b0.z, a0.w, b0.w);
        if (xtr) {
            t0[128 + h] = make_float4(a1.x, b1.x, a1.y, b1.y);
            t1[128 + h] = make_float4(a1.z, b1.z, a1.w, b1.w);
        }
    };

    auto process = [&](int buf, bool emit) {
        const ulonglong2* t0 = (const ulonglong2*)(stg + (buf * 2 + 0) * STAGE_F4);
        const ulonglong2* t1 = (const ulonglong2*)(stg + (buf * 2 + 1) * STAGE_F4);
        // s[m] = (x,y) at column 4h-6+m ; window for out col j: m in [1+j, 11+j]
        u64 s[16];
        #pragma unroll
        for (int k = 0; k < 4; k++) {
            ulonglong2 va = t1[h + k];
            s[4*k + 0] = va.x; s[4*k + 1] = va.y;
            ulonglong2 vb = t0[h + 1 + k];
            s[4*k + 2] = vb.x; s[4*k + 3] = vb.y;
        }

        // ---- E1&E2 packed: base tree over m=1..11 + slide deltas ----
        u64 H12[4];
        {
            u64 p01 = add2(s[1], s[2]),  p23 = add2(s[3], s[4]);
            u64 p45 = add2(s[5], s[6]),  p67 = add2(s[7], s[8]);
            u64 p89 = add2(s[9], s[10]);
            u64 bse = add2(add2(add2(p01, p23), add2(p45, p67)), add2(p89, s[11]));
            u64 dA = sub2(s[12], s[1]);
            u64 dB = sub2(s[13], s[2]);
            u64 dC = sub2(s[14], s[3]);
            H12[0] = bse;
            H12[1] = add2(bse, dA);
            H12[2] = add2(H12[1], dB);
            H12[3] = add2(H12[2], dC);
        }

        // ---- E4 packed (Sum x^2, Sum y^2) ----
        u64 H4p[4];
        {
            u64 q1 = mul2(s[1], s[1]);
            u64 cA = q1;
            cA = fma2(s[2], s[2], cA); cA = fma2(s[3], s[3], cA);
            cA = fma2(s[4], s[4], cA); cA = fma2(s[5], s[5], cA);
            cA = fma2(s[6], s[6], cA);
            u64 cB = mul2(s[7], s[7]);
            cB = fma2(s[8], s[8], cB); cB = fma2(s[9], s[9], cB);
            cB = fma2(s[10], s[10], cB); cB = fma2(s[11], s[11], cB);
            u64 bse = add2(cA, cB);
            u64 q2 = mul2(s[2], s[2]);
            u64 q3 = mul2(s[3], s[3]);
            u64 v1 = fma2(q1, NEG1_PAIR, mul2(s[12], s[12]));
            u64 v2 = fma2(q2, NEG1_PAIR, mul2(s[13], s[13]));
            u64 v3 = fma2(q3, NEG1_PAIR, mul2(s[14], s[14]));
            H4p[0] = bse;
            H4p[1] = add2(bse, v1);
            H4p[2] = add2(H4p[1], v2);
            H4p[3] = add2(H4p[2], v3);
        }

        // ---- E3 scalar (x*y) ----
        float E3[4];
        {
            float2 e1 = upk(s[1]),  e2 = upk(s[2]),  e3 = upk(s[3]);
            float2 e4 = upk(s[4]),  e5 = upk(s[5]),  e6 = upk(s[6]);
            float2 e7 = upk(s[7]),  e8 = upk(s[8]),  e9 = upk(s[9]);
            float2 eA = upk(s[10]), eB = upk(s[11]);
            float2 eC = upk(s[12]), eD = upk(s[13]), eE = upk(s[14]);
            float p1 = e1.x * e1.y;
            float cA = p1;
            cA = fmaf(e2.x, e2.y, cA); cA = fmaf(e3.x, e3.y, cA);
            cA = fmaf(e4.x, e4.y, cA); cA = fmaf(e5.x, e5.y, cA);
            cA = fmaf(e6.x, e6.y, cA);
            float cB = e7.x * e7.y;
            cB = fmaf(e8.x, e8.y, cB); cB = fmaf(e9.x, e9.y, cB);
            cB = fmaf(eA.x, eA.y, cB); cB = fmaf(eB.x, eB.y, cB);
            float p2 = e2.x * e2.y;
            float p3 = e3.x * e3.y;
            E3[0] = cA + cB;
            float u1 = fmaf(eC.x, eC.y, -p1);
            float u2 = fmaf(eD.x, eD.y, -p2);
            float u3 = fmaf(eE.x, eE.y, -p3);
            E3[1] = E3[0] + u1;
            E3[2] = E3[1] + u2;
            E3[3] = E3[2] + u3;
        }

        // ---- pack ring entries (bf16x2 per column pair-quantity) ----
        uint4 nA, nB;
        {
            float2 v0 = upk(H12[0]), v1 = upk(H12[1]), v2 = upk(H12[2]), v3 = upk(H12[3]);
            nA = make_uint4(pkbf(v0.x, v0.y), pkbf(v1.x, v1.y),
                            pkbf(v2.x, v2.y), pkbf(v3.x, v3.y));
            float2 q0 = upk(H4p[0]), q1 = upk(H4p[1]), q2 = upk(H4p[2]), q3 = upk(H4p[3]);
            nB = make_uint4(pkbf(E3[0], q0.x + q0.y), pkbf(E3[1], q1.x + q1.y),
                            pkbf(E3[2], q2.x + q2.y), pkbf(E3[3], q3.x + q3.y));
        }

        // ---- ring swap + vertical running sums (exact telescoping on bf16) ----
        uint4* rp = ring + slot * (2 * TPB) + h;
        uint4 oA = rp[0];
        uint4 oB = rp[TPB];
        rp[0] = nA; rp[TPB] = nB;
        V12[0] = add2(V12[0], sub2(upbf(nA.x), upbf(oA.x)));
        V12[1] = add2(V12[1], sub2(upbf(nA.y), upbf(oA.y)));
        V12[2] = add2(V12[2], sub2(upbf(nA.z), upbf(oA.z)));
        V12[3] = add2(V12[3], sub2(upbf(nA.w), upbf(oA.w)));
        V34[0] = add2(V34[0], sub2(upbf(nB.x), upbf(oB.x)));
        V34[1] = add2(V34[1], sub2(upbf(nB.y), upbf(oB.y)));
        V34[2] = add2(V34[2], sub2(upbf(nB.z), upbf(oB.z)));
        V34[3] = add2(V34[3], sub2(upbf(nB.w), upbf(oB.w)));
        slot = (slot == 10) ? 0 : slot + 1;

        if (emit) {
            float N0, D0, N1, D1, N2, D2, N3, D3;
            float2 a = upk(V12[0]), c = upk(V34[0]);
            ssim_nd(a.x, a.y, c.x, c.y, w, w2, N0, D0);
            a = upk(V12[1]); c = upk(V34[1]);
            ssim_nd(a.x, a.y, c.x, c.y, w, w2, N1, D1);
            a = upk(V12[2]); c = upk(V34[2]);
            ssim_nd(a.x, a.y, c.x, c.y, w, w2, N2, D2);
            a = upk(V12[3]); c = upk(V34[3]);
            ssim_nd(a.x, a.y, c.x, c.y, w, w2, N3, D3);
            acc += __fdividef(fmaf(N0, D1, N1 * D0), D0 * D1);
            acc += __fdividef(fmaf(N2, D3, N3 * D2), D2 * D3);
        }
    };

    // ---- row pipeline: rows r0-5 .. r0+68 (74 rows), emit last 64 ----
    int r = r0 - 5;
    ldg_row(r);
    sts_row(0);
    __syncthreads();
    int pp = 0;

    #pragma unroll 2
    for (int i = 0; i < 10; ++i) {            // warmup, no emit
        ldg_row(r + 1);
        process(pp, false);
        sts_row(pp ^ 1);
        __syncthreads();
        pp ^= 1; ++r;
    }
    #pragma unroll 2
    for (int i = 0; i < 63; ++i) {            // main, emit
        ldg_row(r + 1);
        process(pp, true);
        sts_row(pp ^ 1);
        __syncthreads();
        pp ^= 1; ++r;
    }
    process(pp, true);                        // final row

    // ---- block reduction + last-block finish ----
    #pragma unroll
    for (int o = 16; o > 0; o >>= 1)
        acc += __shfl_xor_sync(0xffffffffu, acc, o);
    __shared__ float wsum[4];
    __shared__ int lastflag;
    int wid = h >> 5, lane = h & 31;
    if (lane == 0) wsum[wid] = acc;
    __syncthreads();
    if (h == 0) {
        float bs = (wsum[0] + wsum[1]) + (wsum[2] + wsum[3]);
        g_part[blockIdx.x] = bs;
        __threadfence();
        unsigned t = atomicAdd(&g_cnt, 1u);
        lastflag = (t == NBLK - 1) ? 1 : 0;
    }
    __syncthreads();

    if (lastflag) {
        volatile float* vp = g_part;
        double d = 0.0;
        #pragma unroll
        for (int k = 0; k < NBLK / TPB; ++k)
            d += (double)vp[h + k * TPB];
        #pragma unroll
        for (int o = 16; o > 0; o >>= 1)
            d += __shfl_xor_sync(0xffffffffu, d, o);
        __shared__ double dsum[4];
        if (lane == 0) dsum[wid] = d;
        __syncthreads();
        if (h == 0) {
            double tot = (dsum[0] + dsum[1]) + (dsum[2] + dsum[3]);
            out[0] = (float)(1.0 - tot * (1.0 / 16777216.0));
            g_cnt = 0;
        }
    }
}

extern "C" void kernel_launch(void* const* d_in, const int* in_sizes, int n_in,
                              void* d_out, int out_size)
{
    const float* img1   = (const float*)d_in[0];
    const float* img2   = (const float*)d_in[1];
    const float* window = (const float*)d_in[2];
    (void)in_sizes; (void)n_in; (void)out_size;

    cudaFuncSetAttribute(ssim_k,
                         cudaFuncAttributeMaxDynamicSharedMemorySize, SMEM_BYTES);
    ssim_k<<<NBLK, TPB, SMEM_BYTES>>>(img1, img2, window, (float*)d_out);
}